// round 16
// baseline (speedup 1.0000x reference)
#include <cuda_runtime.h>
#include <cuda_bf16.h>
#include <cuda_fp16.h>
#include <stdint.h>
#include <math.h>

#define NNODES 50000
#define NEDGES 800000
#define ETOT   (NNODES + NEDGES)   /* 850000, incl. self-loops */
#define NEG_SLOPE 0.2f
#define BN_EPS 1e-5f

// ---------------- device scratch ----------------------------------------------
__device__ __half g_xl1[NNODES * 128];
__device__ __half g_xr1[NNODES * 128];
__device__ float  g_out1[NNODES * 128];
__device__ __half g_xl2[NNODES * 256];
__device__ __half g_xr2[NNODES * 256];
__device__ float  g_tmp2[NNODES * 256];
__device__ float  g_o[NNODES * 128];
__device__ __nv_bfloat16 g_Wh[128 * 512];
__device__ __nv_bfloat16 g_Wl[128 * 512];
__device__ float g_biasc[512];
__device__ int   g_deg[NNODES];
__device__ int   g_off[NNODES + 1];
__device__ int   g_cur[NNODES];
__device__ int   g_csrc[ETOT];
__device__ int   g_bsum[256];
__device__ float g_sum[128], g_sumsq[128], g_scale[128], g_shift[128];
__device__ float g_sum2[128], g_sumsq2[128], g_scale2[128], g_shift2[128];

// ---------------- zero per-call state -----------------------------------------
__global__ void k_zero() {
    int i = blockIdx.x * blockDim.x + threadIdx.x;
    if (i < NNODES) { g_deg[i] = 0; g_cur[i] = 0; }
    if (i < 128) { g_sum[i] = 0.f; g_sumsq[i] = 0.f; g_sum2[i] = 0.f; g_sumsq2[i] = 0.f; }
}

// ---------------- CSR build ----------------------------------------------------
__global__ void k_count(const int* __restrict__ ei) {
    int e = blockIdx.x * blockDim.x + threadIdx.x;
    if (e >= ETOT) return;
    int dst = (e < NEDGES) ? ei[NEDGES + e] : (e - NEDGES);
    atomicAdd(&g_deg[dst], 1);
}

__global__ void k_scan1() {
    __shared__ int buf[256];
    int b = blockIdx.x, t = threadIdx.x;
    int i = b * 256 + t;
    int v = (i < NNODES) ? g_deg[i] : 0;
    buf[t] = v; __syncthreads();
    #pragma unroll
    for (int o = 1; o < 256; o <<= 1) {
        int x = (t >= o) ? buf[t - o] : 0;
        __syncthreads(); buf[t] += x; __syncthreads();
    }
    if (i < NNODES) g_off[i] = buf[t] - v;
    if (t == 255) g_bsum[b] = buf[255];
}
__global__ void k_scan2() {
    __shared__ int buf[256];
    int t = threadIdx.x;
    const int nb = (NNODES + 255) / 256;
    int v = (t < nb) ? g_bsum[t] : 0;
    buf[t] = v; __syncthreads();
    #pragma unroll
    for (int o = 1; o < 256; o <<= 1) {
        int x = (t >= o) ? buf[t - o] : 0;
        __syncthreads(); buf[t] += x; __syncthreads();
    }
    g_bsum[t] = buf[t] - v;
    if (t == 255) g_off[NNODES] = buf[255];
}
__global__ void k_scan3() {
    int i = blockIdx.x * blockDim.x + threadIdx.x;
    if (i < NNODES) g_off[i] += g_bsum[i >> 8];
}

__global__ void k_fill(const int* __restrict__ ei) {
    int e = blockIdx.x * blockDim.x + threadIdx.x;
    if (e >= ETOT) return;
    int src, dst;
    if (e < NEDGES) { src = ei[e]; dst = ei[NEDGES + e]; }
    else { src = dst = e - NEDGES; }
    int pos = g_off[dst] + atomicAdd(&g_cur[dst], 1);
    g_csrc[pos] = src;
}

// ---------------- W pre-split: W_l|W_r -> bf16 hi/lo [K][2*NC] -----------------
__global__ void k_split_W(const float* __restrict__ W_l, const float* __restrict__ b_l,
                          const float* __restrict__ W_r, const float* __restrict__ b_r,
                          int K, int NC) {
    int gid = blockIdx.x * blockDim.x + threadIdx.x;
    int ntot = 2 * NC;
    if (gid < ntot)
        g_biasc[gid] = (gid < NC) ? b_l[gid] : b_r[gid - NC];
    if (gid >= K * ntot) return;
    int k = gid / ntot, col = gid % ntot;
    float v = (col < NC) ? W_l[k * NC + col] : W_r[k * NC + col - NC];
    __nv_bfloat16 h = __float2bfloat16_rn(v);
    g_Wh[gid] = h;
    g_Wl[gid] = __float2bfloat16_rn(v - __bfloat162float(h));
}

// ---------------- tensor-core GEMM: persistent CTA, double-buffer, cp.async ----
#define ASTR 24
#define BSTR 136

__device__ __forceinline__ void ldsm_x4(unsigned addr, unsigned* r) {
    asm volatile("ldmatrix.sync.aligned.m8n8.x4.shared.b16 {%0,%1,%2,%3}, [%4];"
                 : "=r"(r[0]), "=r"(r[1]), "=r"(r[2]), "=r"(r[3]) : "r"(addr));
}
__device__ __forceinline__ void ldsm_x4_t(unsigned addr, unsigned* r) {
    asm volatile("ldmatrix.sync.aligned.m8n8.x4.trans.shared.b16 {%0,%1,%2,%3}, [%4];"
                 : "=r"(r[0]), "=r"(r[1]), "=r"(r[2]), "=r"(r[3]) : "r"(addr));
}
__device__ __forceinline__ void mma_bf16(float* d, const unsigned* a, const unsigned* b) {
    asm volatile("mma.sync.aligned.m16n8k16.row.col.f32.bf16.bf16.f32 "
                 "{%0,%1,%2,%3}, {%4,%5,%6,%7}, {%8,%9}, {%0,%1,%2,%3};"
                 : "+f"(d[0]), "+f"(d[1]), "+f"(d[2]), "+f"(d[3])
                 : "r"(a[0]), "r"(a[1]), "r"(a[2]), "r"(a[3]), "r"(b[0]), "r"(b[1]));
}
__device__ __forceinline__ void cp_async16(unsigned saddr, const void* gaddr) {
    asm volatile("cp.async.cg.shared.global [%0], [%1], 16;" :: "r"(saddr), "l"(gaddr));
}
__device__ __forceinline__ void cp_async_wait() {
    asm volatile("cp.async.commit_group;\n\tcp.async.wait_group 0;" ::: "memory");
}

__device__ __forceinline__ void split8(const float* v, uint4& hi, uint4& lo) {
    unsigned h[8], l[8];
    #pragma unroll
    for (int i = 0; i < 8; i++) {
        __nv_bfloat16 hb = __float2bfloat16_rn(v[i]);
        __nv_bfloat16 lb = __float2bfloat16_rn(v[i] - __bfloat162float(hb));
        h[i] = __bfloat16_as_ushort(hb);
        l[i] = __bfloat16_as_ushort(lb);
    }
    hi = make_uint4(h[0] | (h[1] << 16), h[2] | (h[3] << 16),
                    h[4] | (h[5] << 16), h[6] | (h[7] << 16));
    lo = make_uint4(l[0] | (l[1] << 16), l[2] | (l[3] << 16),
                    l[4] | (l[5] << 16), l[6] | (l[7] << 16));
}

// C[M x Ntot] = A @ [Wl|Wr] + bias; cols < NC_each -> outL, else -> outR
// Persistent: gridDim.x blocks stride over MB*(Ntot/128) tiles.
__global__ __launch_bounds__(256, 2)
void k_mma_gemm(const float* __restrict__ A,
                const float* __restrict__ ascale, const float* __restrict__ ashift,
                __half* __restrict__ outL, __half* __restrict__ outR,
                int M, int Ntot, int NC_each, int MB) {
    constexpr int ABUF = 128 * ASTR;               // 3072 elems (Ah)
    constexpr int BBUF = 16 * BSTR;                // 2176 elems (Bh)
    constexpr int BUFE = 2 * ABUF + 2 * BBUF;      // 10496 elems / buffer
    __shared__ __align__(16) __nv_bfloat16 sbuf[2 * BUFE];   // ~42 KB
    const unsigned BUFB = BUFE * 2;
    const unsigned ALOB = ABUF * 2;
    const unsigned BLOB = BBUF * 2;

    const int K = 128;
    int tid = threadIdx.x, lane = tid & 31, w = tid >> 5;
    int warp_m0 = (w >> 2) * 64, warp_n0 = (w & 3) * 32;

    int arow = tid >> 1, ach = (tid & 1) * 8;
    int brow = tid >> 4, bch = (tid & 15) * 8;

    // ldmatrix read addresses (buffer 0)
    unsigned a_addr[4], b_addr[2];
    {
        int r = warp_m0 + (lane & 15);
        int kh = (lane >> 4) * 8;
        #pragma unroll
        for (int mb = 0; mb < 4; mb++)
            a_addr[mb] = (unsigned)__cvta_generic_to_shared(&sbuf[(r + mb * 16) * ASTR + kh]);
        int krow = ((lane >> 3) & 1) * 8 + (lane & 7);
        int ncol = warp_n0 + (lane >> 4) * 8;
        b_addr[0] = (unsigned)__cvta_generic_to_shared(&sbuf[2 * ABUF + krow * BSTR + ncol]);
        b_addr[1] = (unsigned)__cvta_generic_to_shared(&sbuf[2 * ABUF + krow * BSTR + ncol + 16]);
    }
    unsigned bw = (unsigned)__cvta_generic_to_shared(&sbuf[2 * ABUF + brow * BSTR + bch]);
    const float4 zf4 = make_float4(0.f, 0.f, 0.f, 0.f);

    int ntiles = MB * (Ntot >> 7);
    for (int t = blockIdx.x; t < ntiles; t += gridDim.x) {
        int row0 = (t % MB) * 128;
        int col0 = (t / MB) * 128;

        float acc[4][4][4] = {};
        bool a_ok = (row0 + arow) < M;
        const float* aptr = A + (size_t)(row0 + arow) * K + ach;
        const __nv_bfloat16* whptr = g_Wh + (size_t)brow * Ntot + col0 + bch;
        const __nv_bfloat16* wlptr = g_Wl + (size_t)brow * Ntot + col0 + bch;

        // prologue: tile 0 into buffer 0
        float av[8];
        {
            cp_async16(bw, whptr);
            cp_async16(bw + BLOB, wlptr);
            float4 a0 = a_ok ? *(const float4*)(aptr)     : zf4;
            float4 a1 = a_ok ? *(const float4*)(aptr + 4) : zf4;
            *(float4*)&av[0] = a0; *(float4*)&av[4] = a1;
            if (ascale) {
                #pragma unroll
                for (int i = 0; i < 8; i++) {
                    int c = ach + i;
                    av[i] = fmaxf(fmaf(av[i], ascale[c], ashift[c]), 0.f);
                }
            }
            uint4 ahi, alo;
            split8(av, ahi, alo);
            *(uint4*)&sbuf[arow * ASTR + ach] = ahi;
            *(uint4*)&sbuf[ABUF + arow * ASTR + ach] = alo;
            cp_async_wait();
        }
        __syncthreads();

        unsigned curoff = 0;
        int curbuf = 0;
        for (int k0 = 0; k0 < K; k0 += 16) {
            bool nxt = (k0 + 16) < K;
            int kn = k0 + 16;
            if (nxt) {
                unsigned wdst = bw + (curbuf ^ 1) * BUFB;
                cp_async16(wdst, whptr + (size_t)kn * Ntot);
                cp_async16(wdst + BLOB, wlptr + (size_t)kn * Ntot);
                float4 a0 = a_ok ? *(const float4*)(aptr + kn)     : zf4;
                float4 a1 = a_ok ? *(const float4*)(aptr + kn + 4) : zf4;
                *(float4*)&av[0] = a0; *(float4*)&av[4] = a1;
            }

            unsigned afh[4][4], afl[4][4], bfh[4][2], bfl[4][2];
            #pragma unroll
            for (int mb = 0; mb < 4; mb++) {
                ldsm_x4(a_addr[mb] + curoff, afh[mb]);
                ldsm_x4(a_addr[mb] + curoff + ALOB, afl[mb]);
            }
            #pragma unroll
            for (int nh = 0; nh < 2; nh++) {
                unsigned r[4], rl[4];
                ldsm_x4_t(b_addr[nh] + curoff, r);
                ldsm_x4_t(b_addr[nh] + curoff + BLOB, rl);
                bfh[nh * 2][0] = r[0];  bfh[nh * 2][1] = r[1];
                bfh[nh * 2 + 1][0] = r[2];  bfh[nh * 2 + 1][1] = r[3];
                bfl[nh * 2][0] = rl[0]; bfl[nh * 2][1] = rl[1];
                bfl[nh * 2 + 1][0] = rl[2]; bfl[nh * 2 + 1][1] = rl[3];
            }
            #pragma unroll
            for (int mb = 0; mb < 4; mb++)
                #pragma unroll
                for (int nb = 0; nb < 4; nb++) {
                    mma_bf16(acc[mb][nb], afh[mb], bfh[nb]);
                    mma_bf16(acc[mb][nb], afh[mb], bfl[nb]);
                    mma_bf16(acc[mb][nb], afl[mb], bfh[nb]);
                }

            if (nxt) {
                if (ascale) {
                    #pragma unroll
                    for (int i = 0; i < 8; i++) {
                        int c = kn + ach + i;
                        av[i] = fmaxf(fmaf(av[i], ascale[c], ashift[c]), 0.f);
                    }
                }
                uint4 ahi, alo;
                split8(av, ahi, alo);
                __nv_bfloat16* wb = sbuf + (curbuf ^ 1) * BUFE;
                *(uint4*)&wb[arow * ASTR + ach] = ahi;
                *(uint4*)&wb[ABUF + arow * ASTR + ach] = alo;
                cp_async_wait();
            }
            __syncthreads();
            curbuf ^= 1;
            curoff = curbuf * BUFB;
        }

        // epilogue for this tile
        #pragma unroll
        for (int mb = 0; mb < 4; mb++) {
            int rbase = row0 + warp_m0 + mb * 16 + (lane >> 2);
            #pragma unroll
            for (int nb = 0; nb < 4; nb++) {
                int gc = col0 + warp_n0 + nb * 8 + (lane & 3) * 2;
                float b0 = g_biasc[gc], b1 = g_biasc[gc + 1];
                __half* dst; int cc;
                if (gc < NC_each) { dst = outL; cc = gc; }
                else { dst = outR; cc = gc - NC_each; }
                if (rbase < M)
                    *(__half2*)(dst + (size_t)rbase * NC_each + cc) =
                        __floats2half2_rn(acc[mb][nb][0] + b0, acc[mb][nb][1] + b1);
                if (rbase + 8 < M)
                    *(__half2*)(dst + (size_t)(rbase + 8) * NC_each + cc) =
                        __floats2half2_rn(acc[mb][nb][2] + b0, acc[mb][nb][3] + b1);
            }
        }
        // note: buffer parity after 8 k-iters returns to 0, and the final
        // __syncthreads in the k-loop isolates tiles; no extra sync needed.
    }
}

// ---------------- fused GATv2 edge pass: warp/node, both heads, 2-edge unroll --
// (R11 proven body, exact)
template <int C>
__global__ void k_gat_fused(const __half* __restrict__ xl, const __half* __restrict__ xr,
                            const float* __restrict__ att, const float* __restrict__ bias,
                            float* __restrict__ outp) {
    constexpr int TW = 2 * C;          // 128 or 256
    constexpr int PL = TW / 32;        // 4 or 8 halves per lane
    int n = (blockIdx.x * blockDim.x + threadIdx.x) >> 5;
    int lane = threadIdx.x & 31;
    if (n >= NNODES) return;
    const int col0 = lane * PL;

    float attv[PL], xrv[PL], acc[PL];
    #pragma unroll
    for (int i = 0; i < PL; i++) attv[i] = att[col0 + i];
    {
        const __half* xrp = xr + (size_t)n * TW + col0;
        #pragma unroll
        for (int i = 0; i < PL; i += 2) {
            __half2 t = *(const __half2*)(xrp + i);
            xrv[i] = __low2float(t); xrv[i + 1] = __high2float(t);
        }
    }
    #pragma unroll
    for (int i = 0; i < PL; i++) acc[i] = 0.f;

    float m = -3.4e38f, den = 0.f;
    int p0 = g_off[n], p1 = g_off[n + 1];
    const __half* base = xl + col0;

    uint4 rawA4, rawB4; uint2 rawA2, rawB2;
    if (p0 < p1) {
        int s = g_csrc[p0];
        if (PL == 8) rawA4 = *(const uint4*)(base + (size_t)s * TW);
        else         rawA2 = *(const uint2*)(base + (size_t)s * TW);
    }
    if (p0 + 1 < p1) {
        int s = g_csrc[p0 + 1];
        if (PL == 8) rawB4 = *(const uint4*)(base + (size_t)s * TW);
        else         rawB2 = *(const uint2*)(base + (size_t)s * TW);
    }

    int p = p0;
    while (p + 2 <= p1) {
        float xva[PL], xvb[PL];
        if (PL == 8) {
            const __half2* ha = (const __half2*)&rawA4;
            const __half2* hb = (const __half2*)&rawB4;
            #pragma unroll
            for (int i = 0; i < 4; i++) {
                xva[2*i] = __low2float(ha[i]); xva[2*i+1] = __high2float(ha[i]);
                xvb[2*i] = __low2float(hb[i]); xvb[2*i+1] = __high2float(hb[i]);
            }
        } else {
            const __half2* ha = (const __half2*)&rawA2;
            const __half2* hb = (const __half2*)&rawB2;
            #pragma unroll
            for (int i = 0; i < 2; i++) {
                xva[2*i] = __low2float(ha[i]); xva[2*i+1] = __high2float(ha[i]);
                xvb[2*i] = __low2float(hb[i]); xvb[2*i+1] = __high2float(hb[i]);
            }
        }
        if (p + 2 < p1) {
            int s = g_csrc[p + 2];
            if (PL == 8) rawA4 = *(const uint4*)(base + (size_t)s * TW);
            else         rawA2 = *(const uint2*)(base + (size_t)s * TW);
        }
        if (p + 3 < p1) {
            int s = g_csrc[p + 3];
            if (PL == 8) rawB4 = *(const uint4*)(base + (size_t)s * TW);
            else         rawB2 = *(const uint2*)(base + (size_t)s * TW);
        }
        float lgA = 0.f, lgB = 0.f;
        #pragma unroll
        for (int i = 0; i < PL; i++) {
            float va = xva[i] + xrv[i];
            va = (va > 0.f) ? va : NEG_SLOPE * va;
            lgA = fmaf(va, attv[i], lgA);
            float vb = xvb[i] + xrv[i];
            vb = (vb > 0.f) ? vb : NEG_SLOPE * vb;
            lgB = fmaf(vb, attv[i], lgB);
        }
        #pragma unroll
        for (int o = 8; o > 0; o >>= 1) {
            lgA += __shfl_xor_sync(0xffffffffu, lgA, o);
            lgB += __shfl_xor_sync(0xffffffffu, lgB, o);
        }
        float nm = fmaxf(m, fmaxf(lgA, lgB));
        float sc = __expf(m - nm);
        float ea = __expf(lgA - nm);
        float eb = __expf(lgB - nm);
        den = fmaf(den, sc, ea + eb);
        #pragma unroll
        for (int i = 0; i < PL; i++)
            acc[i] = fmaf(acc[i], sc, fmaf(ea, xva[i], eb * xvb[i]));
        m = nm;
        p += 2;
    }
    if (p < p1) {   // tail edge (data already in rawA)
        float xva[PL];
        if (PL == 8) {
            const __half2* ha = (const __half2*)&rawA4;
            #pragma unroll
            for (int i = 0; i < 4; i++) {
                xva[2*i] = __low2float(ha[i]); xva[2*i+1] = __high2float(ha[i]);
            }
        } else {
            const __half2* ha = (const __half2*)&rawA2;
            #pragma unroll
            for (int i = 0; i < 2; i++) {
                xva[2*i] = __low2float(ha[i]); xva[2*i+1] = __high2float(ha[i]);
            }
        }
        float lgA = 0.f;
        #pragma unroll
        for (int i = 0; i < PL; i++) {
            float va = xva[i] + xrv[i];
            va = (va > 0.f) ? va : NEG_SLOPE * va;
            lgA = fmaf(va, attv[i], lgA);
        }
        #pragma unroll
        for (int o = 8; o > 0; o >>= 1) lgA += __shfl_xor_sync(0xffffffffu, lgA, o);
        float nm = fmaxf(m, lgA);
        float sc = __expf(m - nm);
        float ea = __expf(lgA - nm);
        den = fmaf(den, sc, ea);
        #pragma unroll
        for (int i = 0; i < PL; i++) acc[i] = fmaf(acc[i], sc, ea * xva[i]);
    }

    float inv = 1.f / den;
    float* op = outp + (size_t)n * TW + col0;
    float o[PL];
    #pragma unroll
    for (int i = 0; i < PL; i++)
        o[i] = acc[i] * inv + (bias ? bias[col0 + i] : 0.f);
    #pragma unroll
    for (int i = 0; i < PL; i += 4)
        *(float4*)(op + i) = make_float4(o[i], o[i + 1], o[i + 2], o[i + 3]);
}

// ---------------- BatchNorm stats (float4 + warp-reduced atomics) --------------
__global__ void k_col_stats(const float* __restrict__ X, int rows,
                            float* __restrict__ sum, float* __restrict__ sumsq) {
    int t = threadIdx.x;                  // 256 threads
    int cg = (t >> 3) * 4;                // col group: 4 consecutive cols
    int roff = t & 7;
    float s[4] = {0.f, 0.f, 0.f, 0.f}, q[4] = {0.f, 0.f, 0.f, 0.f};
    for (int r = blockIdx.x * 8 + roff; r < rows; r += gridDim.x * 8) {
        float4 v = *(const float4*)(X + (size_t)r * 128 + cg);
        s[0] += v.x; q[0] = fmaf(v.x, v.x, q[0]);
        s[1] += v.y; q[1] = fmaf(v.y, v.y, q[1]);
        s[2] += v.z; q[2] = fmaf(v.z, v.z, q[2]);
        s[3] += v.w; q[3] = fmaf(v.w, v.w, q[3]);
    }
    #pragma unroll
    for (int o = 1; o < 8; o <<= 1) {
        #pragma unroll
        for (int i = 0; i < 4; i++) {
            s[i] += __shfl_xor_sync(0xffffffffu, s[i], o);
            q[i] += __shfl_xor_sync(0xffffffffu, q[i], o);
        }
    }
    if (roff == 0) {
        #pragma unroll
        for (int i = 0; i < 4; i++) {
            atomicAdd(&sum[cg + i], s[i]);
            atomicAdd(&sumsq[cg + i], q[i]);
        }
    }
}

__global__ void k_finalize_stats(const float* __restrict__ sum, const float* __restrict__ sumsq,
                                 const float* __restrict__ gamma, const float* __restrict__ beta,
                                 float* __restrict__ scale, float* __restrict__ shift, int rows) {
    int c = threadIdx.x;
    float mu  = sum[c] / (float)rows;
    float var = sumsq[c] / (float)rows - mu * mu;
    float inv = rsqrtf(var + BN_EPS);
    float ga = gamma ? gamma[c] : 1.f;
    float be = beta ? beta[c] : 0.f;
    scale[c] = ga * inv;
    shift[c] = be - mu * ga * inv;
}

// head-mean + bias2 + column stats in one pass (writes g_o), vectorized
__global__ void k_combine_stats(const float* __restrict__ bias2) {
    int t = threadIdx.x;
    int cg = (t >> 3) * 4;
    int roff = t & 7;
    float4 bv = *(const float4*)(bias2 + cg);
    float s[4] = {0.f, 0.f, 0.f, 0.f}, q[4] = {0.f, 0.f, 0.f, 0.f};
    for (int r = blockIdx.x * 8 + roff; r < NNODES; r += gridDim.x * 8) {
        float4 a = *(const float4*)(g_tmp2 + (size_t)r * 256 + cg);
        float4 b = *(const float4*)(g_tmp2 + (size_t)r * 256 + 128 + cg);
        float4 v;
        v.x = fmaf(0.5f, a.x + b.x, bv.x);
        v.y = fmaf(0.5f, a.y + b.y, bv.y);
        v.z = fmaf(0.5f, a.z + b.z, bv.z);
        v.w = fmaf(0.5f, a.w + b.w, bv.w);
        *(float4*)(g_o + (size_t)r * 128 + cg) = v;
        s[0] += v.x; q[0] = fmaf(v.x, v.x, q[0]);
        s[1] += v.y; q[1] = fmaf(v.y, v.y, q[1]);
        s[2] += v.z; q[2] = fmaf(v.z, v.z, q[2]);
        s[3] += v.w; q[3] = fmaf(v.w, v.w, q[3]);
    }
    #pragma unroll
    for (int o = 1; o < 8; o <<= 1) {
        #pragma unroll
        for (int i = 0; i < 4; i++) {
            s[i] += __shfl_xor_sync(0xffffffffu, s[i], o);
            q[i] += __shfl_xor_sync(0xffffffffu, q[i], o);
        }
    }
    if (roff == 0) {
        #pragma unroll
        for (int i = 0; i < 4; i++) {
            atomicAdd(&g_sum2[cg + i], s[i]);
            atomicAdd(&g_sumsq2[cg + i], q[i]);
        }
    }
}

// final epilogue (float4): BN (no affine) on cols<64, softplus on cols>=64
__global__ void k_final(float* __restrict__ out) {
    int i4 = blockIdx.x * blockDim.x + threadIdx.x;   // vector index
    if (i4 >= NNODES * 32) return;
    int c = (i4 & 31) * 4;                            // column of first elem
    float4 v = *(const float4*)(g_o + (size_t)i4 * 4);
    float4 o;
    if (c < 64) {
        o.x = v.x * g_scale2[c + 0] + g_shift2[c + 0];
        o.y = v.y * g_scale2[c + 1] + g_shift2[c + 1];
        o.z = v.z * g_scale2[c + 2] + g_shift2[c + 2];
        o.w = v.w * g_scale2[c + 3] + g_shift2[c + 3];
    } else {
        o.x = fmaxf(v.x, 0.f) + log1pf(expf(-fabsf(v.x)));
        o.y = fmaxf(v.y, 0.f) + log1pf(expf(-fabsf(v.y)));
        o.z = fmaxf(v.z, 0.f) + log1pf(expf(-fabsf(v.z)));
        o.w = fmaxf(v.w, 0.f) + log1pf(expf(-fabsf(v.w)));
    }
    *(float4*)(out + (size_t)i4 * 4) = o;
}

// ---------------- launch --------------------------------------------------------
extern "C" void kernel_launch(void* const* d_in, const int* in_sizes, int n_in,
                              void* d_out, int out_size) {
    const float* x     = (const float*)d_in[0];
    const int*   ei    = (const int*)d_in[1];
    const float* W_l1  = (const float*)d_in[2];
    const float* b_l1  = (const float*)d_in[3];
    const float* W_r1  = (const float*)d_in[4];
    const float* b_r1  = (const float*)d_in[5];
    const float* att1  = (const float*)d_in[6];
    const float* bias1 = (const float*)d_in[7];
    const float* gamma1= (const float*)d_in[8];
    const float* beta1 = (const float*)d_in[9];
    const float* W_l2  = (const float*)d_in[10];
    const float* b_l2  = (const float*)d_in[11];
    const float* W_r2  = (const float*)d_in[12];
    const float* b_r2  = (const float*)d_in[13];
    const float* att2  = (const float*)d_in[14];
    const float* bias2 = (const float*)d_in[15];
    float* out = (float*)d_out;

    void* p;
    cudaGetSymbolAddress(&p, g_xl1);   __half* xl1 = (__half*)p;
    cudaGetSymbolAddress(&p, g_xr1);   __half* xr1 = (__half*)p;
    cudaGetSymbolAddress(&p, g_out1);  float* out1 = (float*)p;
    cudaGetSymbolAddress(&p, g_xl2);   __half* xl2 = (__half*)p;
    cudaGetSymbolAddress(&p, g_xr2);   __half* xr2 = (__half*)p;
    cudaGetSymbolAddress(&p, g_tmp2);  float* tmp2 = (float*)p;
    cudaGetSymbolAddress(&p, g_sum);   float* s1   = (float*)p;
    cudaGetSymbolAddress(&p, g_sumsq); float* q1   = (float*)p;
    cudaGetSymbolAddress(&p, g_scale); float* sc1  = (float*)p;
    cudaGetSymbolAddress(&p, g_shift); float* sh1  = (float*)p;
    cudaGetSymbolAddress(&p, g_sum2);  float* s2   = (float*)p;
    cudaGetSymbolAddress(&p, g_sumsq2);float* q2   = (float*)p;
    cudaGetSymbolAddress(&p, g_scale2);float* sc2  = (float*)p;
    cudaGetSymbolAddress(&p, g_shift2);float* sh2  = (float*)p;

    const int NODEW = (NNODES * 32 + 255) / 256;   // warp per node
    const int SCANB = (NNODES + 255) / 256;
    const int MB = (NNODES + 127) / 128;           // 391
    const int PERSIST = 296;                       // 148 SMs x 2 blocks

    // 0) CSR build — GEMM1 kept as the 4th launch (profiler capture slot).
    k_zero<<<SCANB, 256>>>();
    k_count<<<(ETOT + 255) / 256, 256>>>(ei);
    k_split_W<<<(128 * 256 + 255) / 256, 256>>>(W_l1, b_l1, W_r1, b_r1, 128, 128); // 3rd
    k_mma_gemm<<<PERSIST, 256>>>(x, nullptr, nullptr,
                                 xl1, xr1, NNODES, 256, 128, MB);   // 4th launch
    k_scan1<<<SCANB, 256>>>();
    k_scan2<<<1, 256>>>();
    k_scan3<<<SCANB, 256>>>();
    k_fill<<<(ETOT + 255) / 256, 256>>>(ei);

    // 2) conv1 attention + aggregation + bias1 (warp per node, both heads)
    k_gat_fused<64><<<NODEW, 256>>>(xl1, xr1, att1, bias1, out1);

    // 3) BN1 stats
    k_col_stats<<<128, 256>>>(out1, NNODES, s1, q1);
    k_finalize_stats<<<1, 128>>>(s1, q1, gamma1, beta1, sc1, sh1, NNODES);

    // 4) layer2: pre-split W2, fused GEMM (BN1+ReLU folded into A path)
    k_split_W<<<(128 * 512 + 255) / 256, 256>>>(W_l2, b_l2, W_r2, b_r2, 128, 256);
    k_mma_gemm<<<PERSIST, 256>>>(out1, sc1, sh1,
                                 xl2, xr2, NNODES, 512, 256, MB);

    // 5) conv2 attention + aggregation (warp per node)
    k_gat_fused<128><<<NODEW, 256>>>(xl2, xr2, att2, nullptr, tmp2);

    // 6) head-mean + bias2 + BN2 stats, then final epilogue
    k_combine_stats<<<128, 256>>>(bias2);
    k_finalize_stats<<<1, 128>>>(s2, q2, nullptr, nullptr, sc2, sh2, NNODES);
    k_final<<<(NNODES * 32 + 255) / 256, 256>>>(out);
}

// round 17
// speedup vs baseline: 1.0379x; 1.0379x over previous
#include <cuda_runtime.h>
#include <cuda_bf16.h>
#include <cuda_fp16.h>
#include <stdint.h>
#include <math.h>

#define NNODES 50000
#define NEDGES 800000
#define ETOT   (NNODES + NEDGES)   /* 850000, incl. self-loops */
#define NEG_SLOPE 0.2f
#define BN_EPS 1e-5f

// ---------------- device scratch ----------------------------------------------
__device__ __half g_xl1[NNODES * 128];
__device__ __half g_xr1[NNODES * 128];
__device__ float  g_out1[NNODES * 128];
__device__ __half g_xl2[NNODES * 256];
__device__ __half g_xr2[NNODES * 256];
__device__ float  g_tmp2[NNODES * 256];
__device__ float  g_o[NNODES * 128];
__device__ __nv_bfloat16 g_Wh[128 * 512];
__device__ __nv_bfloat16 g_Wl[128 * 512];
__device__ float g_biasc[512];
__device__ int   g_deg[NNODES];
__device__ int   g_off[NNODES + 1];
__device__ int   g_cur[NNODES];
__device__ int   g_csrc[ETOT];
__device__ int   g_bsum[256];
__device__ float g_sum[128], g_sumsq[128], g_scale[128], g_shift[128];
__device__ float g_sum2[128], g_sumsq2[128], g_scale2[128], g_shift2[128];

// ---------------- zero per-call state -----------------------------------------
__global__ void k_zero() {
    int i = blockIdx.x * blockDim.x + threadIdx.x;
    if (i < NNODES) { g_deg[i] = 0; g_cur[i] = 0; }
    if (i < 128) { g_sum[i] = 0.f; g_sumsq[i] = 0.f; g_sum2[i] = 0.f; g_sumsq2[i] = 0.f; }
}

// ---------------- CSR build ----------------------------------------------------
__global__ void k_count(const int* __restrict__ ei) {
    int e = blockIdx.x * blockDim.x + threadIdx.x;
    if (e >= ETOT) return;
    int dst = (e < NEDGES) ? ei[NEDGES + e] : (e - NEDGES);
    atomicAdd(&g_deg[dst], 1);
}

__global__ void k_scan1() {
    __shared__ int buf[256];
    int b = blockIdx.x, t = threadIdx.x;
    int i = b * 256 + t;
    int v = (i < NNODES) ? g_deg[i] : 0;
    buf[t] = v; __syncthreads();
    #pragma unroll
    for (int o = 1; o < 256; o <<= 1) {
        int x = (t >= o) ? buf[t - o] : 0;
        __syncthreads(); buf[t] += x; __syncthreads();
    }
    if (i < NNODES) g_off[i] = buf[t] - v;
    if (t == 255) g_bsum[b] = buf[255];
}
__global__ void k_scan2() {
    __shared__ int buf[256];
    int t = threadIdx.x;
    const int nb = (NNODES + 255) / 256;
    int v = (t < nb) ? g_bsum[t] : 0;
    buf[t] = v; __syncthreads();
    #pragma unroll
    for (int o = 1; o < 256; o <<= 1) {
        int x = (t >= o) ? buf[t - o] : 0;
        __syncthreads(); buf[t] += x; __syncthreads();
    }
    g_bsum[t] = buf[t] - v;
    if (t == 255) g_off[NNODES] = buf[255];
}
__global__ void k_scan3() {
    int i = blockIdx.x * blockDim.x + threadIdx.x;
    if (i < NNODES) g_off[i] += g_bsum[i >> 8];
}

__global__ void k_fill(const int* __restrict__ ei) {
    int e = blockIdx.x * blockDim.x + threadIdx.x;
    if (e >= ETOT) return;
    int src, dst;
    if (e < NEDGES) { src = ei[e]; dst = ei[NEDGES + e]; }
    else { src = dst = e - NEDGES; }
    int pos = g_off[dst] + atomicAdd(&g_cur[dst], 1);
    g_csrc[pos] = src;
}

// ---------------- W pre-split: W_l|W_r -> bf16 hi/lo [K][2*NC] -----------------
__global__ void k_split_W(const float* __restrict__ W_l, const float* __restrict__ b_l,
                          const float* __restrict__ W_r, const float* __restrict__ b_r,
                          int K, int NC) {
    int gid = blockIdx.x * blockDim.x + threadIdx.x;
    int ntot = 2 * NC;
    if (gid < ntot)
        g_biasc[gid] = (gid < NC) ? b_l[gid] : b_r[gid - NC];
    if (gid >= K * ntot) return;
    int k = gid / ntot, col = gid % ntot;
    float v = (col < NC) ? W_l[k * NC + col] : W_r[k * NC + col - NC];
    __nv_bfloat16 h = __float2bfloat16_rn(v);
    g_Wh[gid] = h;
    g_Wl[gid] = __float2bfloat16_rn(v - __bfloat162float(h));
}

// ---------------- tensor-core GEMM: double-buffered, cp.async W (R15) ----------
#define ASTR 24
#define BSTR 136

__device__ __forceinline__ void ldsm_x4(unsigned addr, unsigned* r) {
    asm volatile("ldmatrix.sync.aligned.m8n8.x4.shared.b16 {%0,%1,%2,%3}, [%4];"
                 : "=r"(r[0]), "=r"(r[1]), "=r"(r[2]), "=r"(r[3]) : "r"(addr));
}
__device__ __forceinline__ void ldsm_x4_t(unsigned addr, unsigned* r) {
    asm volatile("ldmatrix.sync.aligned.m8n8.x4.trans.shared.b16 {%0,%1,%2,%3}, [%4];"
                 : "=r"(r[0]), "=r"(r[1]), "=r"(r[2]), "=r"(r[3]) : "r"(addr));
}
__device__ __forceinline__ void mma_bf16(float* d, const unsigned* a, const unsigned* b) {
    asm volatile("mma.sync.aligned.m16n8k16.row.col.f32.bf16.bf16.f32 "
                 "{%0,%1,%2,%3}, {%4,%5,%6,%7}, {%8,%9}, {%0,%1,%2,%3};"
                 : "+f"(d[0]), "+f"(d[1]), "+f"(d[2]), "+f"(d[3])
                 : "r"(a[0]), "r"(a[1]), "r"(a[2]), "r"(a[3]), "r"(b[0]), "r"(b[1]));
}
__device__ __forceinline__ void cp_async16(unsigned saddr, const void* gaddr) {
    asm volatile("cp.async.cg.shared.global [%0], [%1], 16;" :: "r"(saddr), "l"(gaddr));
}
__device__ __forceinline__ void cp_async_wait() {
    asm volatile("cp.async.commit_group;\n\tcp.async.wait_group 0;" ::: "memory");
}

__device__ __forceinline__ void split8(const float* v, uint4& hi, uint4& lo) {
    unsigned h[8], l[8];
    #pragma unroll
    for (int i = 0; i < 8; i++) {
        __nv_bfloat16 hb = __float2bfloat16_rn(v[i]);
        __nv_bfloat16 lb = __float2bfloat16_rn(v[i] - __bfloat162float(hb));
        h[i] = __bfloat16_as_ushort(hb);
        l[i] = __bfloat16_as_ushort(lb);
    }
    hi = make_uint4(h[0] | (h[1] << 16), h[2] | (h[3] << 16),
                    h[4] | (h[5] << 16), h[6] | (h[7] << 16));
    lo = make_uint4(l[0] | (l[1] << 16), l[2] | (l[3] << 16),
                    l[4] | (l[5] << 16), l[6] | (l[7] << 16));
}

// C[M x Ntot] = A @ [Wl|Wr] + bias; cols < NC_each -> outL, else -> outR
__global__ __launch_bounds__(256, 2)
void k_mma_gemm(const float* __restrict__ A,
                const float* __restrict__ ascale, const float* __restrict__ ashift,
                __half* __restrict__ outL, __half* __restrict__ outR,
                int M, int Ntot, int NC_each) {
    constexpr int ABUF = 128 * ASTR;               // 3072 elems (Ah)
    constexpr int BBUF = 16 * BSTR;                // 2176 elems (Bh)
    constexpr int BUFE = 2 * ABUF + 2 * BBUF;      // 10496 elems / buffer
    __shared__ __align__(16) __nv_bfloat16 sbuf[2 * BUFE];   // ~42 KB
    const unsigned BUFB = BUFE * 2;                // bytes per buffer
    const unsigned ALOB = ABUF * 2;                // Ah -> Al byte offset
    const unsigned BLOB = BBUF * 2;                // Bh -> Bl byte offset

    const int K = 128;
    int tid = threadIdx.x, lane = tid & 31, w = tid >> 5;
    int row0 = blockIdx.x * 128;
    int col0 = blockIdx.y * 128;
    int warp_m0 = (w >> 2) * 64, warp_n0 = (w & 3) * 32;

    float acc[4][4][4] = {};

    int arow = tid >> 1, ach = (tid & 1) * 8;
    int brow = tid >> 4, bch = (tid & 15) * 8;
    bool a_ok = (row0 + arow) < M;

    // read-side ldmatrix addresses for buffer 0
    unsigned a_addr[4], b_addr[2];
    {
        int r = warp_m0 + (lane & 15);
        int kh = (lane >> 4) * 8;
        #pragma unroll
        for (int mb = 0; mb < 4; mb++)
            a_addr[mb] = (unsigned)__cvta_generic_to_shared(&sbuf[(r + mb * 16) * ASTR + kh]);
        int krow = ((lane >> 3) & 1) * 8 + (lane & 7);
        int ncol = warp_n0 + (lane >> 4) * 8;
        b_addr[0] = (unsigned)__cvta_generic_to_shared(&sbuf[2 * ABUF + krow * BSTR + ncol]);
        b_addr[1] = (unsigned)__cvta_generic_to_shared(&sbuf[2 * ABUF + krow * BSTR + ncol + 16]);
    }
    // write-side smem addresses for buffer 0
    unsigned bw = (unsigned)__cvta_generic_to_shared(&sbuf[2 * ABUF + brow * BSTR + bch]);

    const float* aptr = A + (size_t)(row0 + arow) * K + ach;
    const __nv_bfloat16* whptr = g_Wh + (size_t)brow * Ntot + col0 + bch;
    const __nv_bfloat16* wlptr = g_Wl + (size_t)brow * Ntot + col0 + bch;
    const float4 zf4 = make_float4(0.f, 0.f, 0.f, 0.f);

    // ---- prologue: tile 0 into buffer 0 ----
    float av[8];
    {
        cp_async16(bw, whptr);
        cp_async16(bw + BLOB, wlptr);
        float4 a0 = a_ok ? *(const float4*)(aptr)     : zf4;
        float4 a1 = a_ok ? *(const float4*)(aptr + 4) : zf4;
        *(float4*)&av[0] = a0; *(float4*)&av[4] = a1;
        if (ascale) {
            #pragma unroll
            for (int i = 0; i < 8; i++) {
                int c = ach + i;
                av[i] = fmaxf(fmaf(av[i], ascale[c], ashift[c]), 0.f);
            }
        }
        uint4 ahi, alo;
        split8(av, ahi, alo);
        __nv_bfloat16* wb = sbuf;
        *(uint4*)&wb[arow * ASTR + ach] = ahi;
        *(uint4*)&wb[ABUF + arow * ASTR + ach] = alo;
        cp_async_wait();
    }
    __syncthreads();

    unsigned curoff = 0;          // byte offset of the buffer being consumed
    int curbuf = 0;
    for (int k0 = 0; k0 < K; k0 += 16) {
        bool nxt = (k0 + 16) < K;
        int kn = k0 + 16;
        if (nxt) {
            // W tile kn -> other buffer via cp.async (no regs, no convert)
            unsigned wdst = bw + (curbuf ^ 1) * BUFB;
            cp_async16(wdst, whptr + (size_t)kn * Ntot);
            cp_async16(wdst + BLOB, wlptr + (size_t)kn * Ntot);
            // A tile kn -> registers (fp32)
            float4 a0 = a_ok ? *(const float4*)(aptr + kn)     : zf4;
            float4 a1 = a_ok ? *(const float4*)(aptr + kn + 4) : zf4;
            *(float4*)&av[0] = a0; *(float4*)&av[4] = a1;
        }

        // ---- MMA on current buffer ----
        unsigned afh[4][4], afl[4][4], bfh[4][2], bfl[4][2];
        #pragma unroll
        for (int mb = 0; mb < 4; mb++) {
            ldsm_x4(a_addr[mb] + curoff, afh[mb]);
            ldsm_x4(a_addr[mb] + curoff + ALOB, afl[mb]);
        }
        #pragma unroll
        for (int nh = 0; nh < 2; nh++) {
            unsigned r[4], rl[4];
            ldsm_x4_t(b_addr[nh] + curoff, r);
            ldsm_x4_t(b_addr[nh] + curoff + BLOB, rl);
            bfh[nh * 2][0] = r[0];  bfh[nh * 2][1] = r[1];
            bfh[nh * 2 + 1][0] = r[2];  bfh[nh * 2 + 1][1] = r[3];
            bfl[nh * 2][0] = rl[0]; bfl[nh * 2][1] = rl[1];
            bfl[nh * 2 + 1][0] = rl[2]; bfl[nh * 2 + 1][1] = rl[3];
        }
        #pragma unroll
        for (int mb = 0; mb < 4; mb++)
            #pragma unroll
            for (int nb = 0; nb < 4; nb++) {
                mma_bf16(acc[mb][nb], afh[mb], bfh[nb]);
                mma_bf16(acc[mb][nb], afh[mb], bfl[nb]);
                mma_bf16(acc[mb][nb], afl[mb], bfh[nb]);
            }

        if (nxt) {
            if (ascale) {
                #pragma unroll
                for (int i = 0; i < 8; i++) {
                    int c = kn + ach + i;
                    av[i] = fmaxf(fmaf(av[i], ascale[c], ashift[c]), 0.f);
                }
            }
            uint4 ahi, alo;
            split8(av, ahi, alo);
            __nv_bfloat16* wb = sbuf + (curbuf ^ 1) * BUFE;
            *(uint4*)&wb[arow * ASTR + ach] = ahi;
            *(uint4*)&wb[ABUF + arow * ASTR + ach] = alo;
            cp_async_wait();
        }
        __syncthreads();
        curbuf ^= 1;
        curoff = curbuf * BUFB;
    }

    #pragma unroll
    for (int mb = 0; mb < 4; mb++) {
        int rbase = row0 + warp_m0 + mb * 16 + (lane >> 2);
        #pragma unroll
        for (int nb = 0; nb < 4; nb++) {
            int gc = col0 + warp_n0 + nb * 8 + (lane & 3) * 2;
            float b0 = g_biasc[gc], b1 = g_biasc[gc + 1];
            __half* dst; int cc;
            if (gc < NC_each) { dst = outL; cc = gc; }
            else { dst = outR; cc = gc - NC_each; }
            if (rbase < M)
                *(__half2*)(dst + (size_t)rbase * NC_each + cc) =
                    __floats2half2_rn(acc[mb][nb][0] + b0, acc[mb][nb][1] + b1);
            if (rbase + 8 < M)
                *(__half2*)(dst + (size_t)(rbase + 8) * NC_each + cc) =
                    __floats2half2_rn(acc[mb][nb][2] + b0, acc[mb][nb][3] + b1);
        }
    }
}

// ---------------- fused GATv2 edge pass: warp/node, both heads, 2-edge unroll --
// (R11 proven body, exact)
template <int C>
__global__ void k_gat_fused(const __half* __restrict__ xl, const __half* __restrict__ xr,
                            const float* __restrict__ att, const float* __restrict__ bias,
                            float* __restrict__ outp) {
    constexpr int TW = 2 * C;          // 128 or 256
    constexpr int PL = TW / 32;        // 4 or 8 halves per lane
    int n = (blockIdx.x * blockDim.x + threadIdx.x) >> 5;
    int lane = threadIdx.x & 31;
    if (n >= NNODES) return;
    const int col0 = lane * PL;

    float attv[PL], xrv[PL], acc[PL];
    #pragma unroll
    for (int i = 0; i < PL; i++) attv[i] = att[col0 + i];
    {
        const __half* xrp = xr + (size_t)n * TW + col0;
        #pragma unroll
        for (int i = 0; i < PL; i += 2) {
            __half2 t = *(const __half2*)(xrp + i);
            xrv[i] = __low2float(t); xrv[i + 1] = __high2float(t);
        }
    }
    #pragma unroll
    for (int i = 0; i < PL; i++) acc[i] = 0.f;

    float m = -3.4e38f, den = 0.f;
    int p0 = g_off[n], p1 = g_off[n + 1];
    const __half* base = xl + col0;

    uint4 rawA4, rawB4; uint2 rawA2, rawB2;
    if (p0 < p1) {
        int s = g_csrc[p0];
        if (PL == 8) rawA4 = *(const uint4*)(base + (size_t)s * TW);
        else         rawA2 = *(const uint2*)(base + (size_t)s * TW);
    }
    if (p0 + 1 < p1) {
        int s = g_csrc[p0 + 1];
        if (PL == 8) rawB4 = *(const uint4*)(base + (size_t)s * TW);
        else         rawB2 = *(const uint2*)(base + (size_t)s * TW);
    }

    int p = p0;
    while (p + 2 <= p1) {
        float xva[PL], xvb[PL];
        if (PL == 8) {
            const __half2* ha = (const __half2*)&rawA4;
            const __half2* hb = (const __half2*)&rawB4;
            #pragma unroll
            for (int i = 0; i < 4; i++) {
                xva[2*i] = __low2float(ha[i]); xva[2*i+1] = __high2float(ha[i]);
                xvb[2*i] = __low2float(hb[i]); xvb[2*i+1] = __high2float(hb[i]);
            }
        } else {
            const __half2* ha = (const __half2*)&rawA2;
            const __half2* hb = (const __half2*)&rawB2;
            #pragma unroll
            for (int i = 0; i < 2; i++) {
                xva[2*i] = __low2float(ha[i]); xva[2*i+1] = __high2float(ha[i]);
                xvb[2*i] = __low2float(hb[i]); xvb[2*i+1] = __high2float(hb[i]);
            }
        }
        if (p + 2 < p1) {
            int s = g_csrc[p + 2];
            if (PL == 8) rawA4 = *(const uint4*)(base + (size_t)s * TW);
            else         rawA2 = *(const uint2*)(base + (size_t)s * TW);
        }
        if (p + 3 < p1) {
            int s = g_csrc[p + 3];
            if (PL == 8) rawB4 = *(const uint4*)(base + (size_t)s * TW);
            else         rawB2 = *(const uint2*)(base + (size_t)s * TW);
        }
        float lgA = 0.f, lgB = 0.f;
        #pragma unroll
        for (int i = 0; i < PL; i++) {
            float va = xva[i] + xrv[i];
            va = (va > 0.f) ? va : NEG_SLOPE * va;
            lgA = fmaf(va, attv[i], lgA);
            float vb = xvb[i] + xrv[i];
            vb = (vb > 0.f) ? vb : NEG_SLOPE * vb;
            lgB = fmaf(vb, attv[i], lgB);
        }
        #pragma unroll
        for (int o = 8; o > 0; o >>= 1) {
            lgA += __shfl_xor_sync(0xffffffffu, lgA, o);
            lgB += __shfl_xor_sync(0xffffffffu, lgB, o);
        }
        float nm = fmaxf(m, fmaxf(lgA, lgB));
        float sc = __expf(m - nm);
        float ea = __expf(lgA - nm);
        float eb = __expf(lgB - nm);
        den = fmaf(den, sc, ea + eb);
        #pragma unroll
        for (int i = 0; i < PL; i++)
            acc[i] = fmaf(acc[i], sc, fmaf(ea, xva[i], eb * xvb[i]));
        m = nm;
        p += 2;
    }
    if (p < p1) {   // tail edge (data already in rawA)
        float xva[PL];
        if (PL == 8) {
            const __half2* ha = (const __half2*)&rawA4;
            #pragma unroll
            for (int i = 0; i < 4; i++) {
                xva[2*i] = __low2float(ha[i]); xva[2*i+1] = __high2float(ha[i]);
            }
        } else {
            const __half2* ha = (const __half2*)&rawA2;
            #pragma unroll
            for (int i = 0; i < 2; i++) {
                xva[2*i] = __low2float(ha[i]); xva[2*i+1] = __high2float(ha[i]);
            }
        }
        float lgA = 0.f;
        #pragma unroll
        for (int i = 0; i < PL; i++) {
            float va = xva[i] + xrv[i];
            va = (va > 0.f) ? va : NEG_SLOPE * va;
            lgA = fmaf(va, attv[i], lgA);
        }
        #pragma unroll
        for (int o = 8; o > 0; o >>= 1) lgA += __shfl_xor_sync(0xffffffffu, lgA, o);
        float nm = fmaxf(m, lgA);
        float sc = __expf(m - nm);
        float ea = __expf(lgA - nm);
        den = fmaf(den, sc, ea);
        #pragma unroll
        for (int i = 0; i < PL; i++) acc[i] = fmaf(acc[i], sc, ea * xva[i]);
    }

    float inv = 1.f / den;
    float* op = outp + (size_t)n * TW + col0;
    float o[PL];
    #pragma unroll
    for (int i = 0; i < PL; i++)
        o[i] = acc[i] * inv + (bias ? bias[col0 + i] : 0.f);
    #pragma unroll
    for (int i = 0; i < PL; i += 4)
        *(float4*)(op + i) = make_float4(o[i], o[i + 1], o[i + 2], o[i + 3]);
}

// ---------------- BatchNorm stats (float4 + warp-reduced atomics) --------------
__global__ void k_col_stats(const float* __restrict__ X, int rows,
                            float* __restrict__ sum, float* __restrict__ sumsq) {
    int t = threadIdx.x;                  // 256 threads
    int cg = (t >> 3) * 4;                // col group: 4 consecutive cols
    int roff = t & 7;
    float s[4] = {0.f, 0.f, 0.f, 0.f}, q[4] = {0.f, 0.f, 0.f, 0.f};
    for (int r = blockIdx.x * 8 + roff; r < rows; r += gridDim.x * 8) {
        float4 v = *(const float4*)(X + (size_t)r * 128 + cg);
        s[0] += v.x; q[0] = fmaf(v.x, v.x, q[0]);
        s[1] += v.y; q[1] = fmaf(v.y, v.y, q[1]);
        s[2] += v.z; q[2] = fmaf(v.z, v.z, q[2]);
        s[3] += v.w; q[3] = fmaf(v.w, v.w, q[3]);
    }
    #pragma unroll
    for (int o = 1; o < 8; o <<= 1) {
        #pragma unroll
        for (int i = 0; i < 4; i++) {
            s[i] += __shfl_xor_sync(0xffffffffu, s[i], o);
            q[i] += __shfl_xor_sync(0xffffffffu, q[i], o);
        }
    }
    if (roff == 0) {
        #pragma unroll
        for (int i = 0; i < 4; i++) {
            atomicAdd(&sum[cg + i], s[i]);
            atomicAdd(&sumsq[cg + i], q[i]);
        }
    }
}

__global__ void k_finalize_stats(const float* __restrict__ sum, const float* __restrict__ sumsq,
                                 const float* __restrict__ gamma, const float* __restrict__ beta,
                                 float* __restrict__ scale, float* __restrict__ shift, int rows) {
    int c = threadIdx.x;
    float mu  = sum[c] / (float)rows;
    float var = sumsq[c] / (float)rows - mu * mu;
    float inv = rsqrtf(var + BN_EPS);
    float ga = gamma ? gamma[c] : 1.f;
    float be = beta ? beta[c] : 0.f;
    scale[c] = ga * inv;
    shift[c] = be - mu * ga * inv;
}

// head-mean + bias2 + column stats in one pass (writes g_o), vectorized
__global__ void k_combine_stats(const float* __restrict__ bias2) {
    int t = threadIdx.x;
    int cg = (t >> 3) * 4;
    int roff = t & 7;
    float4 bv = *(const float4*)(bias2 + cg);
    float s[4] = {0.f, 0.f, 0.f, 0.f}, q[4] = {0.f, 0.f, 0.f, 0.f};
    for (int r = blockIdx.x * 8 + roff; r < NNODES; r += gridDim.x * 8) {
        float4 a = *(const float4*)(g_tmp2 + (size_t)r * 256 + cg);
        float4 b = *(const float4*)(g_tmp2 + (size_t)r * 256 + 128 + cg);
        float4 v;
        v.x = fmaf(0.5f, a.x + b.x, bv.x);
        v.y = fmaf(0.5f, a.y + b.y, bv.y);
        v.z = fmaf(0.5f, a.z + b.z, bv.z);
        v.w = fmaf(0.5f, a.w + b.w, bv.w);
        *(float4*)(g_o + (size_t)r * 128 + cg) = v;
        s[0] += v.x; q[0] = fmaf(v.x, v.x, q[0]);
        s[1] += v.y; q[1] = fmaf(v.y, v.y, q[1]);
        s[2] += v.z; q[2] = fmaf(v.z, v.z, q[2]);
        s[3] += v.w; q[3] = fmaf(v.w, v.w, q[3]);
    }
    #pragma unroll
    for (int o = 1; o < 8; o <<= 1) {
        #pragma unroll
        for (int i = 0; i < 4; i++) {
            s[i] += __shfl_xor_sync(0xffffffffu, s[i], o);
            q[i] += __shfl_xor_sync(0xffffffffu, q[i], o);
        }
    }
    if (roff == 0) {
        #pragma unroll
        for (int i = 0; i < 4; i++) {
            atomicAdd(&g_sum2[cg + i], s[i]);
            atomicAdd(&g_sumsq2[cg + i], q[i]);
        }
    }
}

// final epilogue (float4): BN (no affine) on cols<64, softplus on cols>=64
__global__ void k_final(float* __restrict__ out) {
    int i4 = blockIdx.x * blockDim.x + threadIdx.x;   // vector index
    if (i4 >= NNODES * 32) return;
    int c = (i4 & 31) * 4;                            // column of first elem
    float4 v = *(const float4*)(g_o + (size_t)i4 * 4);
    float4 o;
    if (c < 64) {
        o.x = v.x * g_scale2[c + 0] + g_shift2[c + 0];
        o.y = v.y * g_scale2[c + 1] + g_shift2[c + 1];
        o.z = v.z * g_scale2[c + 2] + g_shift2[c + 2];
        o.w = v.w * g_scale2[c + 3] + g_shift2[c + 3];
    } else {
        o.x = fmaxf(v.x, 0.f) + log1pf(expf(-fabsf(v.x)));
        o.y = fmaxf(v.y, 0.f) + log1pf(expf(-fabsf(v.y)));
        o.z = fmaxf(v.z, 0.f) + log1pf(expf(-fabsf(v.z)));
        o.w = fmaxf(v.w, 0.f) + log1pf(expf(-fabsf(v.w)));
    }
    *(float4*)(out + (size_t)i4 * 4) = o;
}

// ---------------- launch --------------------------------------------------------
extern "C" void kernel_launch(void* const* d_in, const int* in_sizes, int n_in,
                              void* d_out, int out_size) {
    const float* x     = (const float*)d_in[0];
    const int*   ei    = (const int*)d_in[1];
    const float* W_l1  = (const float*)d_in[2];
    const float* b_l1  = (const float*)d_in[3];
    const float* W_r1  = (const float*)d_in[4];
    const float* b_r1  = (const float*)d_in[5];
    const float* att1  = (const float*)d_in[6];
    const float* bias1 = (const float*)d_in[7];
    const float* gamma1= (const float*)d_in[8];
    const float* beta1 = (const float*)d_in[9];
    const float* W_l2  = (const float*)d_in[10];
    const float* b_l2  = (const float*)d_in[11];
    const float* W_r2  = (const float*)d_in[12];
    const float* b_r2  = (const float*)d_in[13];
    const float* att2  = (const float*)d_in[14];
    const float* bias2 = (const float*)d_in[15];
    float* out = (float*)d_out;

    void* p;
    cudaGetSymbolAddress(&p, g_xl1);   __half* xl1 = (__half*)p;
    cudaGetSymbolAddress(&p, g_xr1);   __half* xr1 = (__half*)p;
    cudaGetSymbolAddress(&p, g_out1);  float* out1 = (float*)p;
    cudaGetSymbolAddress(&p, g_xl2);   __half* xl2 = (__half*)p;
    cudaGetSymbolAddress(&p, g_xr2);   __half* xr2 = (__half*)p;
    cudaGetSymbolAddress(&p, g_tmp2);  float* tmp2 = (float*)p;
    cudaGetSymbolAddress(&p, g_sum);   float* s1   = (float*)p;
    cudaGetSymbolAddress(&p, g_sumsq); float* q1   = (float*)p;
    cudaGetSymbolAddress(&p, g_scale); float* sc1  = (float*)p;
    cudaGetSymbolAddress(&p, g_shift); float* sh1  = (float*)p;
    cudaGetSymbolAddress(&p, g_sum2);  float* s2   = (float*)p;
    cudaGetSymbolAddress(&p, g_sumsq2);float* q2   = (float*)p;
    cudaGetSymbolAddress(&p, g_scale2);float* sc2  = (float*)p;
    cudaGetSymbolAddress(&p, g_shift2);float* sh2  = (float*)p;

    const int NODEW = (NNODES * 32 + 255) / 256;   // warp per node
    const int SCANB = (NNODES + 255) / 256;
    const int MB = (NNODES + 127) / 128;           // 391

    // 0) CSR build — GEMM1 kept as the 4th launch (profiler capture slot).
    k_zero<<<SCANB, 256>>>();
    k_count<<<(ETOT + 255) / 256, 256>>>(ei);
    k_split_W<<<(128 * 256 + 255) / 256, 256>>>(W_l1, b_l1, W_r1, b_r1, 128, 128); // 3rd
    k_mma_gemm<<<dim3(MB, 2), 256>>>(x, nullptr, nullptr,
                                     xl1, xr1, NNODES, 256, 128);   // 4th launch
    k_scan1<<<SCANB, 256>>>();
    k_scan2<<<1, 256>>>();
    k_scan3<<<SCANB, 256>>>();
    k_fill<<<(ETOT + 255) / 256, 256>>>(ei);

    // 2) conv1 attention + aggregation + bias1 (warp per node, both heads)
    k_gat_fused<64><<<NODEW, 256>>>(xl1, xr1, att1, bias1, out1);

    // 3) BN1 stats
    k_col_stats<<<128, 256>>>(out1, NNODES, s1, q1);
    k_finalize_stats<<<1, 128>>>(s1, q1, gamma1, beta1, sc1, sh1, NNODES);

    // 4) layer2: pre-split W2, fused GEMM (BN1+ReLU folded into A path)
    k_split_W<<<(128 * 512 + 255) / 256, 256>>>(W_l2, b_l2, W_r2, b_r2, 128, 256);
    k_mma_gemm<<<dim3(MB, 4), 256>>>(out1, sc1, sh1,
                                     xl2, xr2, NNODES, 512, 256);

    // 5) conv2 attention + aggregation (warp per node)
    k_gat_fused<128><<<NODEW, 256>>>(xl2, xr2, att2, nullptr, tmp2);

    // 6) head-mean + bias2 + BN2 stats, then final epilogue
    k_combine_stats<<<128, 256>>>(bias2);
    k_finalize_stats<<<1, 128>>>(s2, q2, nullptr, nullptr, sc2, sh2, NNODES);
    k_final<<<(NNODES * 32 + 255) / 256, 256>>>(out);
}